// round 2
// baseline (speedup 1.0000x reference)
#include <cuda_runtime.h>
#include <math.h>

#define NN      6000
#define DD      128
#define RR      1000
#define MAXDEG  128
#define MAXRDEG 64
#define NB      12000     /* 2*NN: both branches stacked */
#define NWB     1500      /* NB/8 rows-per-block grid */
#define MAXN_   0.996f    /* 1 - 4e-3 */

/* ------------------------- static scratch (no allocs) ------------------------- */
__device__ __align__(16) float g_seq[(long)NB*3*DD];       /* [n][l][d] */
__device__ __align__(16) float g_hh [(long)NB*2*DD];       /* [n][h*128+e] */
__device__ float g_es0[NB], g_ed0[NB], g_es1[NB], g_ed1[NB];
__device__ __align__(16) float g_q [(long)NB*3*2*DD];
__device__ __align__(16) float g_k [(long)NB*3*2*DD];
__device__ __align__(16) float g_v [(long)NB*3*2*DD];
__device__ __align__(16) float g_o [(long)NB*3*2*DD];
__device__ __align__(16) float g_of[(long)NB*3*DD];
__device__ __align__(16) float g_u [(long)NB*DD];
__device__ __align__(16) float g_t [(long)NB*DD];
__device__ __align__(16) float g_y [(long)NB*DD];
__device__ __align__(16) float g_w [(long)NB*DD];
__device__ __align__(16) float g_w2[(long)NB*DD];
__device__ __align__(16) float g_Wt[2*DD*DD];
__device__ __align__(16) float g_Bcat[2*DD*2*DD];          /* [L][d][h*128+e] */
__device__ int g_adj_cols[(long)NB*MAXDEG];
__device__ int g_adj_deg[NB];
__device__ int g_rel_cols[(long)NB*MAXRDEG];
__device__ int g_rel_deg[NB];

/* ------------------------- warp reduction helpers ----------------------------- */
__device__ __forceinline__ float wrsum(float x) {
#pragma unroll
    for (int o = 16; o; o >>= 1) x += __shfl_xor_sync(0xffffffffu, x, o);
    return x;
}
__device__ __forceinline__ float wrmax(float x) {
#pragma unroll
    for (int o = 16; o; o >>= 1) x = fmaxf(x, __shfl_xor_sync(0xffffffffu, x, o));
    return x;
}
__device__ __forceinline__ float dot4(float4 a, float4 b) {
    return a.x*b.x + a.y*b.y + a.z*b.z + a.w*b.w;
}

/* ------------------------- f32x2 packed FMA ----------------------------------- */
__device__ __forceinline__ unsigned long long splat2(float x) {
    unsigned long long r;
    asm("mov.b64 %0, {%1, %1};" : "=l"(r) : "f"(x));
    return r;
}
__device__ __forceinline__ void ffma2(unsigned long long& d, unsigned long long a,
                                      unsigned long long b) {
    asm("fma.rn.f32x2 %0, %1, %2, %0;" : "+l"(d) : "l"(a), "l"(b));
}

/* ------------------------- CSR builders --------------------------------------- */
__global__ void k_build_adj(const float* __restrict__ a0, const float* __restrict__ a1) {
    int row = blockIdx.x, b = blockIdx.y;
    const float4* adj = (const float4*)((b ? a1 : a0) + (long)row * NN);
    __shared__ int cnt;
    if (threadIdx.x == 0) cnt = 0;
    __syncthreads();
    int* mc = g_adj_cols + (long)(b*NN + row) * MAXDEG;
    for (int c = threadIdx.x; c < NN/4; c += blockDim.x) {
        float4 v = adj[c];
        if (v.x > 0.f) { int p = atomicAdd(&cnt, 1); if (p < MAXDEG) mc[p] = c*4;   }
        if (v.y > 0.f) { int p = atomicAdd(&cnt, 1); if (p < MAXDEG) mc[p] = c*4+1; }
        if (v.z > 0.f) { int p = atomicAdd(&cnt, 1); if (p < MAXDEG) mc[p] = c*4+2; }
        if (v.w > 0.f) { int p = atomicAdd(&cnt, 1); if (p < MAXDEG) mc[p] = c*4+3; }
    }
    __syncthreads();
    if (threadIdx.x == 0) g_adj_deg[b*NN + row] = min(cnt, MAXDEG);
}
__global__ void k_build_rel(const float* __restrict__ a0, const float* __restrict__ a1) {
    int row = blockIdx.x, b = blockIdx.y;
    const float4* adj = (const float4*)((b ? a1 : a0) + (long)row * RR);
    __shared__ int cnt;
    if (threadIdx.x == 0) cnt = 0;
    __syncthreads();
    int* mc = g_rel_cols + (long)(b*NN + row) * MAXRDEG;
    for (int c = threadIdx.x; c < RR/4; c += blockDim.x) {
        float4 v = adj[c];
        if (v.x > 0.f) { int p = atomicAdd(&cnt, 1); if (p < MAXRDEG) mc[p] = c*4;   }
        if (v.y > 0.f) { int p = atomicAdd(&cnt, 1); if (p < MAXRDEG) mc[p] = c*4+1; }
        if (v.z > 0.f) { int p = atomicAdd(&cnt, 1); if (p < MAXRDEG) mc[p] = c*4+2; }
        if (v.w > 0.f) { int p = atomicAdd(&cnt, 1); if (p < MAXRDEG) mc[p] = c*4+3; }
    }
    __syncthreads();
    if (threadIdx.x == 0) g_rel_deg[b*NN + row] = min(cnt, MAXRDEG);
}

/* ------------------------- rel aggregator (warp/row) -------------------------- */
__global__ __launch_bounds__(256) void k_relagg(const float* __restrict__ r0,
                                                const float* __restrict__ r1,
                                                float* __restrict__ out) {
    int w = blockIdx.x*8 + (threadIdx.x >> 5);
    if (w >= NB) return;
    int lane = threadIdx.x & 31;
    int b = w / NN, row = w - b*NN;
    const float* remb = b ? r1 : r0;
    const int* cols = g_rel_cols + (long)w * MAXRDEG;
    int deg = g_rel_deg[w];
    float4 acc = make_float4(0.f, 0.f, 0.f, 0.f);
    for (int j = 0; j < deg; j++) {
        int c = __ldg(&cols[j]);
        float4 v = *(const float4*)(remb + (long)c*DD + lane*4);
        acc.x += v.x; acc.y += v.y; acc.z += v.z; acc.w += v.w;
    }
    float inv = 1.f / (float)deg;
    float4 r = make_float4(acc.x*inv, acc.y*inv, acc.z*inv, acc.w*inv);
    *(float4*)(out + (long)b*NN*256 + (long)row*256 + 128 + lane*4) = r;
    *(float4*)(out + (long)(2+b)*NN*256 + (long)row*256 + 128 + lane*4) = r;
}

/* ------------------------- seq slot-0 copy ------------------------------------ */
__global__ __launch_bounds__(256) void k_seq0(const float* __restrict__ e0,
                                              const float* __restrict__ e1) {
    int idx = blockIdx.x*256 + threadIdx.x;       /* over NB*32 float4 */
    if (idx >= NB*32) return;
    int n = idx >> 5, c = idx & 31;
    int b = n / NN, row = n - b*NN;
    const float4* src = (const float4*)((b ? e1 : e0) + (long)row*DD);
    ((float4*)(g_seq + (long)n*384))[c] = src[c];
}

/* ------------------------- B concat for GAT heads ----------------------------- */
__global__ void k_bcat(const float* __restrict__ W) {  /* W: [L][H][D][E] */
    int idx = blockIdx.x*256 + threadIdx.x;            /* 2*2*128*128 = 65536 */
    if (idx >= 2*2*DD*DD) return;
    int e = idx & 127, d = (idx >> 7) & 127, h = (idx >> 14) & 1, L = idx >> 15;
    g_Bcat[((long)L*DD + d)*256 + h*128 + e] = W[idx];
}

/* ------------------------- SGEMM with f32x2, z-selects B/C -------------------- */
__global__ __launch_bounds__(256, 2)
void k_gemm(const float* __restrict__ A, int lda,
            const float* __restrict__ B0, const float* __restrict__ B1,
            const float* __restrict__ B2, int ldb,
            float* __restrict__ C0, float* __restrict__ C1, float* __restrict__ C2,
            int ldc, int M, int K) {
    const int BK = 32;
    __shared__ float As[BK][128 + 4];
    __shared__ float Bs[BK][128 + 4];
    const float* B = (blockIdx.z == 0) ? B0 : (blockIdx.z == 1) ? B1 : B2;
    float* C = (blockIdx.z == 0) ? C0 : (blockIdx.z == 1) ? C1 : C2;
    int tid = threadIdx.x;
    int bm = blockIdx.y * 128, bn = blockIdx.x * 128;
    int tx = tid & 15, ty = tid >> 4;
    unsigned long long acc[8][4];
#pragma unroll
    for (int i = 0; i < 8; i++)
#pragma unroll
        for (int j = 0; j < 4; j++) acc[i][j] = 0ull;

    for (int k0 = 0; k0 < K; k0 += BK) {
#pragma unroll
        for (int i = 0; i < 4; i++) {
            int lin = tid + i*256;
            int r = lin >> 3, c = (lin & 7) << 2;
            float4 av = make_float4(0.f, 0.f, 0.f, 0.f);
            if (bm + r < M) av = *(const float4*)(A + (long)(bm+r)*lda + k0 + c);
            As[c  ][r] = av.x; As[c+1][r] = av.y; As[c+2][r] = av.z; As[c+3][r] = av.w;
        }
#pragma unroll
        for (int i = 0; i < 4; i++) {
            int lin = tid + i*256;
            int r = lin >> 5, c = (lin & 31) << 2;
            *(float4*)&Bs[r][c] = *(const float4*)(B + (long)(k0+r)*ldb + bn + c);
        }
        __syncthreads();
#pragma unroll
        for (int kk = 0; kk < BK; kk++) {
            float a[8];
            *(float4*)&a[0] = *(const float4*)&As[kk][ty*8];
            *(float4*)&a[4] = *(const float4*)&As[kk][ty*8 + 4];
            unsigned long long b2[4];
            const unsigned long long* bp = (const unsigned long long*)&Bs[kk][tx*8];
            b2[0] = bp[0]; b2[1] = bp[1]; b2[2] = bp[2]; b2[3] = bp[3];
#pragma unroll
            for (int i = 0; i < 8; i++) {
                unsigned long long a2 = splat2(a[i]);
#pragma unroll
                for (int j = 0; j < 4; j++) ffma2(acc[i][j], a2, b2[j]);
            }
        }
        __syncthreads();
    }
#pragma unroll
    for (int i = 0; i < 8; i++) {
        int r = bm + ty*8 + i;
        if (r < M) {
            float cv[8];
#pragma unroll
            for (int j = 0; j < 4; j++) {
                cv[2*j]   = __uint_as_float((unsigned)(acc[i][j] & 0xffffffffull));
                cv[2*j+1] = __uint_as_float((unsigned)(acc[i][j] >> 32));
            }
            *(float4*)(C + (long)r*ldc + bn + tx*8)     = *(float4*)&cv[0];
            *(float4*)(C + (long)r*ldc + bn + tx*8 + 4) = *(float4*)&cv[4];
        }
    }
}

/* ------------------------- GAT: es/ed dots (warp/row) ------------------------- */
__global__ __launch_bounds__(256) void k_esed(const float* __restrict__ asrc,
                                              const float* __restrict__ adst) {
    int w = blockIdx.x*8 + (threadIdx.x >> 5);
    if (w >= NB) return;
    int lane = threadIdx.x & 31;
    float4 h0 = *(const float4*)(g_hh + (long)w*256 + lane*4);
    float4 h1 = *(const float4*)(g_hh + (long)w*256 + 128 + lane*4);
    float4 as0 = *(const float4*)(asrc + lane*4);
    float4 ad0 = *(const float4*)(adst + lane*4);
    float4 as1 = *(const float4*)(asrc + 128 + lane*4);
    float4 ad1 = *(const float4*)(adst + 128 + lane*4);
    float v0 = wrsum(dot4(h0, as0));
    float v1 = wrsum(dot4(h0, ad0));
    float v2 = wrsum(dot4(h1, as1));
    float v3 = wrsum(dot4(h1, ad1));
    if (lane == 0) { g_es0[w] = v0; g_ed0[w] = v1; g_es1[w] = v2; g_ed1[w] = v3; }
}

/* ------------------------- GAT: masked softmax aggregation (warp/row) --------- */
__global__ __launch_bounds__(256) void k_gat_agg(int lslot) {
    int w = blockIdx.x*8 + (threadIdx.x >> 5);
    if (w >= NB) return;
    int lane = threadIdx.x & 31;
    int b = w / NN;
    int deg = g_adj_deg[w];
    const int* cols = g_adj_cols + (long)w * MAXDEG;
    int creg[4]; float e0r[4], e1r[4];
    float es0 = g_es0[w], es1 = g_es1[w];
    float m0 = -1e30f, m1 = -1e30f;
#pragma unroll
    for (int i = 0; i < 4; i++) {
        int j = i*32 + lane;
        creg[i] = 0; e0r[i] = -1e30f; e1r[i] = -1e30f;
        if (j < deg) {
            int c = cols[j]; creg[i] = c;
            float t0 = es0 + g_ed0[b*NN + c]; e0r[i] = (t0 > 0.f) ? t0 : 0.2f*t0;
            float t1 = es1 + g_ed1[b*NN + c]; e1r[i] = (t1 > 0.f) ? t1 : 0.2f*t1;
            m0 = fmaxf(m0, e0r[i]); m1 = fmaxf(m1, e1r[i]);
        }
    }
    m0 = wrmax(m0); m1 = wrmax(m1);
    float s0 = 0.f, s1 = 0.f;
    float p0r[4], p1r[4];
#pragma unroll
    for (int i = 0; i < 4; i++) {
        int j = i*32 + lane;
        p0r[i] = (j < deg) ? expf(e0r[i] - m0) : 0.f;
        p1r[i] = (j < deg) ? expf(e1r[i] - m1) : 0.f;
        s0 += p0r[i]; s1 += p1r[i];
    }
    s0 = wrsum(s0); s1 = wrsum(s1);
    float inv0 = 1.f / s0, inv1 = 1.f / s1;
    float4 a0 = make_float4(0.f, 0.f, 0.f, 0.f);
    float4 a1 = make_float4(0.f, 0.f, 0.f, 0.f);
    for (int i = 0; i < 4 && i*32 < deg; i++) {
        for (int l = 0; l < 32; l++) {
            int j = i*32 + l;
            if (j >= deg) break;                    /* uniform across warp */
            int   c  = __shfl_sync(0xffffffffu, creg[i], l);
            float w0 = __shfl_sync(0xffffffffu, p0r[i], l) * inv0;
            float w1 = __shfl_sync(0xffffffffu, p1r[i], l) * inv1;
            const float* hp = g_hh + (long)(b*NN + c)*256;
            float4 h0 = *(const float4*)(hp + lane*4);
            float4 h1 = *(const float4*)(hp + 128 + lane*4);
            a0.x += w0*h0.x; a0.y += w0*h0.y; a0.z += w0*h0.z; a0.w += w0*h0.w;
            a1.x += w1*h1.x; a1.y += w1*h1.y; a1.z += w1*h1.z; a1.w += w1*h1.w;
        }
    }
    float4 mv = make_float4(0.5f*(a0.x+a1.x), 0.5f*(a0.y+a1.y),
                            0.5f*(a0.z+a1.z), 0.5f*(a0.w+a1.w));
    float4 ev;
    ev.x = (mv.x > 0.f) ? mv.x : expm1f(mv.x);
    ev.y = (mv.y > 0.f) ? mv.y : expm1f(mv.y);
    ev.z = (mv.z > 0.f) ? mv.z : expm1f(mv.z);
    ev.w = (mv.w > 0.f) ? mv.w : expm1f(mv.w);
    float ss = wrsum(dot4(ev, ev));
    float nrm = 1.f / fmaxf(sqrtf(ss), 1e-12f);
    float4 r = make_float4(ev.x*nrm, ev.y*nrm, ev.z*nrm, ev.w*nrm);
    *(float4*)(g_seq + ((long)w*3 + lslot)*DD + lane*4) = r;
}

/* ------------------------- MHA attention (warp/node) -------------------------- */
__global__ __launch_bounds__(256) void k_mha() {
    int w = blockIdx.x*8 + (threadIdx.x >> 5);
    if (w >= NB) return;
    int lane = threadIdx.x & 31;
    const float* qp = g_q + (long)w*768;
    const float* kp = g_k + (long)w*768;
    const float* vp = g_v + (long)w*768;
    float4 q4[3][2], k4[3][2], v4[3][2];
#pragma unroll
    for (int l = 0; l < 3; l++)
#pragma unroll
        for (int h = 0; h < 2; h++) {
            q4[l][h] = *(const float4*)(qp + l*256 + h*128 + lane*4);
            k4[l][h] = *(const float4*)(kp + l*256 + h*128 + lane*4);
            v4[l][h] = *(const float4*)(vp + l*256 + h*128 + lane*4);
        }
    float sc[2][3][3];
#pragma unroll
    for (int h = 0; h < 2; h++)
#pragma unroll
        for (int l = 0; l < 3; l++)
#pragma unroll
            for (int m = 0; m < 3; m++)
                sc[h][l][m] = wrsum(dot4(q4[l][h], k4[m][h])) * 0.08838834764831845f;
#pragma unroll
    for (int h = 0; h < 2; h++)
#pragma unroll
        for (int l = 0; l < 3; l++) {
            float a0 = sc[h][l][0], a1 = sc[h][l][1], a2 = sc[h][l][2];
            float m = fmaxf(a0, fmaxf(a1, a2));
            float e0 = expf(a0 - m), e1 = expf(a1 - m), e2 = expf(a2 - m);
            float inv = 1.f / (e0 + e1 + e2);
            float4 o;
            o.x = (e0*v4[0][h].x + e1*v4[1][h].x + e2*v4[2][h].x) * inv;
            o.y = (e0*v4[0][h].y + e1*v4[1][h].y + e2*v4[2][h].y) * inv;
            o.z = (e0*v4[0][h].z + e1*v4[1][h].z + e2*v4[2][h].z) * inv;
            o.w = (e0*v4[0][h].w + e1*v4[1][h].w + e2*v4[2][h].w) * inv;
            *(float4*)(g_o + ((long)w*3 + l)*256 + h*128 + lane*4) = o;
        }
}

/* ------------------------- residual + LN + mean (warp/row) -------------------- */
__global__ __launch_bounds__(256) void k_ln(const float* __restrict__ g,
                                            const float* __restrict__ bb,
                                            float* __restrict__ out) {
    int w = blockIdx.x*8 + (threadIdx.x >> 5);
    if (w >= NB) return;
    int lane = threadIdx.x & 31;
    int b = w / NN, row = w - b*NN;
    float4 g4 = *(const float4*)(g + lane*4);
    float4 b4 = *(const float4*)(bb + lane*4);
    float4 acc = make_float4(0.f, 0.f, 0.f, 0.f);
#pragma unroll
    for (int l = 0; l < 3; l++) {
        float4 v0 = *(const float4*)(g_of + ((long)w*3 + l)*DD + lane*4);
        float4 v1 = *(const float4*)(g_seq + ((long)w*3 + l)*DD + lane*4);
        float4 v = make_float4(v0.x+v1.x, v0.y+v1.y, v0.z+v1.z, v0.w+v1.w);
        float s  = wrsum(v.x + v.y + v.z + v.w);
        float s2 = wrsum(dot4(v, v));
        float mu  = s * (1.f/128.f);
        float var = s2 * (1.f/128.f) - mu*mu;
        float is = rsqrtf(var + 1e-6f);
        acc.x += g4.x*(v.x - mu)*is + b4.x;
        acc.y += g4.y*(v.y - mu)*is + b4.y;
        acc.z += g4.z*(v.z - mu)*is + b4.z;
        acc.w += g4.w*(v.w - mu)*is + b4.w;
    }
    float4 r = make_float4(acc.x*(1.f/3.f), acc.y*(1.f/3.f),
                           acc.z*(1.f/3.f), acc.w*(1.f/3.f));
    *(float4*)(out + (long)b*NN*256 + (long)row*256 + lane*4) = r;
}

/* ------------------------- HGC pieces (warp/row) ------------------------------ */
__global__ __launch_bounds__(256) void k_u0(const float* __restrict__ e0,
                                            const float* __restrict__ e1) {
    int w = blockIdx.x*8 + (threadIdx.x >> 5);
    if (w >= NB) return;
    int lane = threadIdx.x & 31;
    int b = w / NN, row = w - b*NN;
    float4 x = *(const float4*)((b ? e1 : e0) + (long)row*DD + lane*4);
    float s = wrsum(dot4(x, x));
    float n0 = fmaxf(sqrtf(s), 1e-15f);
    float ne = tanhf(n0);
    float pe = (ne > MAXN_) ? MAXN_/ne : 1.f;
    float np = fmaxf(ne*pe, 1e-15f);
    float c  = atanhf(fminf(np, 1.f - 1e-7f)) / np * (ne / n0) * pe;
    float4 r = make_float4(c*x.x, c*x.y, c*x.z, c*x.w);
    *(float4*)(g_u + (long)w*DD + lane*4) = r;
}

__global__ void k_transW(const float* __restrict__ W) {
    int j = blockIdx.y, dd = blockIdx.x, e = threadIdx.x;
    g_Wt[j*DD*DD + dd*DD + e] = W[j*DD*DD + e*DD + dd];
}

__global__ __launch_bounds__(256) void k_hgc_bias(const float* __restrict__ T,
                                                  const float* __restrict__ bvec,
                                                  float* __restrict__ Y) {
    int w = blockIdx.x*8 + (threadIdx.x >> 5);
    if (w >= NB) return;
    int lane = threadIdx.x & 31;
    float4 t4 = *(const float4*)(T + (long)w*DD + lane*4);
    float4 b4 = *(const float4*)(bvec + lane*4);
    float s0 = wrsum(dot4(t4, t4));
    float s1 = wrsum(dot4(b4, b4));
    float s2 = wrsum(dot4(t4, b4));
    float nt = fmaxf(sqrtf(s0), 1e-15f);
    float et = tanhf(nt);
    float pt = (et > MAXN_) ? MAXN_/et : 1.f;
    float cm = (et/nt) * pt;
    float x2 = (et*pt) * (et*pt);
    float nb = fmaxf(sqrtf(s1), 1e-15f);
    float eb = tanhf(nb);
    float pb = (eb > MAXN_) ? MAXN_/eb : 1.f;
    float cb = (eb/nb) * pb;
    float y2 = (eb*pb) * (eb*pb);
    float xy = cm * cb * s2;
    float den = fmaxf(1.f + 2.f*xy + x2*y2, 1e-15f);
    float fA = (1.f + 2.f*xy + y2) * cm / den;
    float fB = (1.f - x2) * cb / den;
    float4 r = make_float4(fA*t4.x + fB*b4.x, fA*t4.y + fB*b4.y,
                           fA*t4.z + fB*b4.z, fA*t4.w + fB*b4.w);
    float s3 = wrsum(dot4(r, r));
    float nr = fmaxf(sqrtf(s3), 1e-15f);
    float pr = (nr > MAXN_) ? MAXN_/nr : 1.f;
    float np = fmaxf(nr*pr, 1e-15f);
    float c2 = atanhf(fminf(np, 1.f - 1e-7f)) / np * pr;
    *(float4*)(Y + (long)w*DD + lane*4) =
        make_float4(c2*r.x, c2*r.y, c2*r.z, c2*r.w);
}

__global__ __launch_bounds__(256) void k_hgc_agg(const float* __restrict__ Y,
                                                 float* __restrict__ W) {
    int w = blockIdx.x*8 + (threadIdx.x >> 5);
    if (w >= NB) return;
    int lane = threadIdx.x & 31;
    int b = w / NN;
    const int* cols = g_adj_cols + (long)w * MAXDEG;
    int deg = g_adj_deg[w];
    float4 acc = make_float4(0.f, 0.f, 0.f, 0.f);
    for (int j = 0; j < deg; j++) {
        int c = __ldg(&cols[j]);
        float4 v = *(const float4*)(Y + (long)(b*NN + c)*DD + lane*4);
        acc.x += v.x; acc.y += v.y; acc.z += v.z; acc.w += v.w;
    }
    float inv = 1.f / (float)deg;
    float4 z = make_float4(acc.x*inv, acc.y*inv, acc.z*inv, acc.w*inv);
    float4 rz = make_float4(fmaxf(z.x, 0.f), fmaxf(z.y, 0.f),
                            fmaxf(z.z, 0.f), fmaxf(z.w, 0.f));
    float s0 = wrsum(dot4(z, z));
    float s1 = wrsum(dot4(rz, rz));
    float nz = fmaxf(sqrtf(s0), 1e-15f);
    float e1 = tanhf(nz);
    float p1 = (e1 > MAXN_) ? MAXN_/e1 : 1.f;
    float cH = (e1/nz) * p1;
    float nH = fmaxf(e1*p1, 1e-15f);
    float cT = atanhf(fminf(nH, 1.f - 1e-7f)) / nH * cH;
    float nt2 = fmaxf(cT * sqrtf(s1), 1e-15f);
    float e2 = tanhf(nt2);
    float p2 = (e2 > MAXN_) ? MAXN_/e2 : 1.f;
    float hcoef = (e2/nt2) * p2 * cT;
    float nH2 = fmaxf(e2*p2, 1e-15f);
    float c2 = atanhf(fminf(nH2, 1.f - 1e-7f)) / nH2;
    float cc = c2 * hcoef;
    *(float4*)(W + (long)w*DD + lane*4) =
        make_float4(cc*rz.x, cc*rz.y, cc*rz.z, cc*rz.w);
}

__global__ __launch_bounds__(256) void k_hs(const float* __restrict__ e0,
                                            const float* __restrict__ e1,
                                            float* __restrict__ out) {
    int w = blockIdx.x*8 + (threadIdx.x >> 5);
    if (w >= NB) return;
    int lane = threadIdx.x & 31;
    int b = w / NN, row = w - b*NN;
    float4 e = *(const float4*)((b ? e1 : e0) + (long)row*DD + lane*4);
    float4 v = *(const float4*)(g_w2 + (long)w*DD + lane*4);
    *(float4*)(out + (long)(2+b)*NN*256 + (long)row*256 + lane*4) =
        make_float4(e.x+v.x, e.y+v.y, e.z+v.z, e.w+v.w);
}

/* ------------------------- host driver ----------------------------------------- */
extern "C" void kernel_launch(void* const* d_in, const int* in_sizes, int n_in,
                              void* d_out, int out_size) {
    const float* ent_sr    = (const float*)d_in[0];
    const float* ent_tg    = (const float*)d_in[1];
    const float* rel_sr    = (const float*)d_in[2];
    const float* rel_tg    = (const float*)d_in[3];
    const float* adj_sr    = (const float*)d_in[4];
    const float* adj_tg    = (const float*)d_in[5];
    const float* rel_adj_sr= (const float*)d_in[6];
    const float* rel_adj_tg= (const float*)d_in[7];
    const float* gat_W     = (const float*)d_in[8];
    const float* gat_a_src = (const float*)d_in[9];
    const float* gat_a_dst = (const float*)d_in[10];
    const float* Wq        = (const float*)d_in[11];
    const float* Wk        = (const float*)d_in[12];
    const float* Wv        = (const float*)d_in[13];
    const float* Wfc       = (const float*)d_in[14];
    const float* ln_g      = (const float*)d_in[15];
    const float* ln_b      = (const float*)d_in[16];
    const float* hgc_W     = (const float*)d_in[17];
    const float* hgc_b     = (const float*)d_in[18];
    float* out = (float*)d_out;

    float *seq, *hh, *q, *k, *v, *o, *of, *u, *t, *y, *w, *w2, *Wt, *Bcat;
    cudaGetSymbolAddress((void**)&seq, g_seq);
    cudaGetSymbolAddress((void**)&hh,  g_hh);
    cudaGetSymbolAddress((void**)&q,   g_q);
    cudaGetSymbolAddress((void**)&k,   g_k);
    cudaGetSymbolAddress((void**)&v,   g_v);
    cudaGetSymbolAddress((void**)&o,   g_o);
    cudaGetSymbolAddress((void**)&of,  g_of);
    cudaGetSymbolAddress((void**)&u,   g_u);
    cudaGetSymbolAddress((void**)&t,   g_t);
    cudaGetSymbolAddress((void**)&y,   g_y);
    cudaGetSymbolAddress((void**)&w,   g_w);
    cudaGetSymbolAddress((void**)&w2,  g_w2);
    cudaGetSymbolAddress((void**)&Wt,  g_Wt);
    cudaGetSymbolAddress((void**)&Bcat,g_Bcat);

    dim3 gGAT(2, (12000 + 127) / 128, 1);    /* N=256 */
    dim3 gQKV(2, (36000 + 127) / 128, 3);
    dim3 gFC (1, (36000 + 127) / 128, 1);
    dim3 gHGC(1, (12000 + 127) / 128, 1);

    /* sparsify + prep */
    k_build_adj<<<dim3(NN, 2), 256>>>(adj_sr, adj_tg);
    k_build_rel<<<dim3(NN, 2), 256>>>(rel_adj_sr, rel_adj_tg);
    k_relagg<<<NWB, 256>>>(rel_sr, rel_tg, out);
    k_seq0<<<NWB, 256>>>(ent_sr, ent_tg);
    k_bcat<<<256, 256>>>(gat_W);
    k_transW<<<dim3(DD, 2), DD>>>(hgc_W);

    /* GAT x2 (both heads fused as N=256 GEMM) */
    for (int L = 0; L < 2; L++) {
        const float* A = seq + L * DD;   /* slot L, lda = 384 */
        const float* B = Bcat + (long)L * DD * 256;
        k_gemm<<<gGAT, 256>>>(A, 384, B, B, B, 256, hh, hh, hh, 256, 12000, 128);
        k_esed<<<NWB, 256>>>(gat_a_src + L*2*DD, gat_a_dst + L*2*DD);
        k_gat_agg<<<NWB, 256>>>(L + 1);
    }

    /* MHA */
    k_gemm<<<gQKV, 256>>>(seq, 128, Wq, Wk, Wv, 256, q, k, v, 256, 36000, 128);
    k_mha<<<NWB, 256>>>();
    k_gemm<<<gFC, 256>>>(o, 256, Wfc, Wfc, Wfc, 128, of, of, of, 128, 36000, 256);
    k_ln<<<NWB, 256>>>(ln_g, ln_b, out);

    /* HGC encoder */
    k_u0<<<NWB, 256>>>(ent_sr, ent_tg);
    k_gemm<<<gHGC, 256>>>(u, 128, Wt, Wt, Wt, 128, t, t, t, 128, 12000, 128);
    k_hgc_bias<<<NWB, 256>>>(t, hgc_b, y);
    k_hgc_agg<<<NWB, 256>>>(y, w);
    k_gemm<<<gHGC, 256>>>(w, 128, Wt + DD*DD, Wt + DD*DD, Wt + DD*DD, 128,
                          t, t, t, 128, 12000, 128);
    k_hgc_bias<<<NWB, 256>>>(t, hgc_b + DD, y);
    k_hgc_agg<<<NWB, 256>>>(y, w2);
    k_hs<<<NWB, 256>>>(ent_sr, ent_tg, out);
}

// round 5
// speedup vs baseline: 1.7405x; 1.7405x over previous
#include <cuda_runtime.h>
#include <math.h>

#define NN      6000
#define DD      128
#define RR      1000
#define MAXDEG  128
#define MAXRDEG 64
#define NB      12000     /* 2*NN: both branches stacked */
#define NWB     1500      /* NB/8 warp-per-row grid */
#define MAXN_   0.996f    /* 1 - 4e-3 */

/* ------------------------- static scratch (no allocs) ------------------------- */
__device__ __align__(16) float g_seq[(long)NB*3*DD];       /* [n][l][d] */
__device__ __align__(16) float g_mix[(long)NB*2*DD];       /* [n][h*128+d] x-space mixed */
__device__ __align__(16) float g_mv [(long)NB*DD];         /* GAT layer pre-activation */
__device__ float g_es0[NB], g_ed0[NB], g_es1[NB], g_ed1[NB];
__device__ __align__(16) float g_y2[(long)NB*3*2*DD];      /* y = x @ Gcat */
__device__ __align__(16) float g_z [(long)NB*3*2*DD];      /* attn-mixed x, per head */
__device__ __align__(16) float g_of[(long)NB*3*DD];
__device__ __align__(16) float g_u [(long)NB*DD];
__device__ __align__(16) float g_t [(long)NB*DD];
__device__ __align__(16) float g_y [(long)NB*DD];
__device__ __align__(16) float g_w [(long)NB*DD];
__device__ __align__(16) float g_w2[(long)NB*DD];
__device__ __align__(16) float g_Wt[2*DD*DD];
__device__ __align__(16) float g_G [DD*2*DD];              /* [d1][h*128+d2] */
__device__ __align__(16) float g_P [2*DD*DD];              /* [h*128+d][d2]  */
__device__ __align__(16) float g_wsd[2*2*2*DD];            /* [L][s][h][d] */
__device__ int g_adj_cols[(long)NB*MAXDEG];
__device__ int g_adj_deg[NB];
__device__ int g_rel_cols[(long)NB*MAXRDEG];
__device__ int g_rel_deg[NB];

/* ------------------------- warp helpers --------------------------------------- */
__device__ __forceinline__ float wrsum(float x) {
#pragma unroll
    for (int o = 16; o; o >>= 1) x += __shfl_xor_sync(0xffffffffu, x, o);
    return x;
}
__device__ __forceinline__ float wrmax(float x) {
#pragma unroll
    for (int o = 16; o; o >>= 1) x = fmaxf(x, __shfl_xor_sync(0xffffffffu, x, o));
    return x;
}
__device__ __forceinline__ float dot4(float4 a, float4 b) {
    return a.x*b.x + a.y*b.y + a.z*b.z + a.w*b.w;
}

/* ------------------------- CSR builders --------------------------------------- */
__global__ void k_build_adj(const float* __restrict__ a0, const float* __restrict__ a1) {
    int row = blockIdx.x, b = blockIdx.y;
    const float4* adj = (const float4*)((b ? a1 : a0) + (long)row * NN);
    __shared__ int cnt;
    if (threadIdx.x == 0) cnt = 0;
    __syncthreads();
    int* mc = g_adj_cols + (long)(b*NN + row) * MAXDEG;
    for (int c = threadIdx.x; c < NN/4; c += blockDim.x) {
        float4 v = adj[c];
        if (v.x > 0.f) { int p = atomicAdd(&cnt, 1); if (p < MAXDEG) mc[p] = c*4;   }
        if (v.y > 0.f) { int p = atomicAdd(&cnt, 1); if (p < MAXDEG) mc[p] = c*4+1; }
        if (v.z > 0.f) { int p = atomicAdd(&cnt, 1); if (p < MAXDEG) mc[p] = c*4+2; }
        if (v.w > 0.f) { int p = atomicAdd(&cnt, 1); if (p < MAXDEG) mc[p] = c*4+3; }
    }
    __syncthreads();
    if (threadIdx.x == 0) g_adj_deg[b*NN + row] = min(cnt, MAXDEG);
}
__global__ void k_build_rel(const float* __restrict__ a0, const float* __restrict__ a1) {
    int row = blockIdx.x, b = blockIdx.y;
    const float4* adj = (const float4*)((b ? a1 : a0) + (long)row * RR);
    __shared__ int cnt;
    if (threadIdx.x == 0) cnt = 0;
    __syncthreads();
    int* mc = g_rel_cols + (long)(b*NN + row) * MAXRDEG;
    for (int c = threadIdx.x; c < RR/4; c += blockDim.x) {
        float4 v = adj[c];
        if (v.x > 0.f) { int p = atomicAdd(&cnt, 1); if (p < MAXRDEG) mc[p] = c*4;   }
        if (v.y > 0.f) { int p = atomicAdd(&cnt, 1); if (p < MAXRDEG) mc[p] = c*4+1; }
        if (v.z > 0.f) { int p = atomicAdd(&cnt, 1); if (p < MAXRDEG) mc[p] = c*4+2; }
        if (v.w > 0.f) { int p = atomicAdd(&cnt, 1); if (p < MAXRDEG) mc[p] = c*4+3; }
    }
    __syncthreads();
    if (threadIdx.x == 0) g_rel_deg[b*NN + row] = min(cnt, MAXRDEG);
}

/* ------------------------- rel aggregator (warp/row) -------------------------- */
__global__ __launch_bounds__(256) void k_relagg(const float* __restrict__ r0,
                                                const float* __restrict__ r1,
                                                float* __restrict__ out) {
    int w = blockIdx.x*8 + (threadIdx.x >> 5);
    if (w >= NB) return;
    int lane = threadIdx.x & 31;
    int b = w / NN, row = w - b*NN;
    const float* remb = b ? r1 : r0;
    const int* cols = g_rel_cols + (long)w * MAXRDEG;
    int deg = g_rel_deg[w];
    float4 acc = make_float4(0.f, 0.f, 0.f, 0.f);
    for (int j = 0; j < deg; j++) {
        int c = __ldg(&cols[j]);
        float4 v = *(const float4*)(remb + (long)c*DD + lane*4);
        acc.x += v.x; acc.y += v.y; acc.z += v.z; acc.w += v.w;
    }
    float inv = 1.f / (float)deg;
    float4 r = make_float4(acc.x*inv, acc.y*inv, acc.z*inv, acc.w*inv);
    *(float4*)(out + (long)b*NN*256 + (long)row*256 + 128 + lane*4) = r;
    *(float4*)(out + (long)(2+b)*NN*256 + (long)row*256 + 128 + lane*4) = r;
}

/* ------------------------- seq slot-0 copy ------------------------------------ */
__global__ __launch_bounds__(256) void k_seq0(const float* __restrict__ e0,
                                              const float* __restrict__ e1) {
    int idx = blockIdx.x*256 + threadIdx.x;       /* over NB*32 float4 */
    if (idx >= NB*32) return;
    int n = idx >> 5, c = idx & 31;
    int b = n / NN, row = n - b*NN;
    const float4* src = (const float4*)((b ? e1 : e0) + (long)row*DD);
    ((float4*)(g_seq + (long)n*384))[c] = src[c];
}

/* ------------------------- precompute kernels --------------------------------- */
/* G[d1][h*128+d2] = sum_e Wq[d1][h*128+e] * Wk[d2][h*128+e] */
__global__ void k_precomp_G(const float* __restrict__ Wq, const float* __restrict__ Wk) {
    int d1 = blockIdx.x, t = threadIdx.x;           /* t = h*128+d2 */
    int h = t >> 7, d2 = t & 127;
    float acc = 0.f;
    const float* wq = Wq + d1*256 + h*128;
    const float* wk = Wk + d2*256 + h*128;
    for (int e = 0; e < 128; e++) acc += wq[e] * wk[e];
    g_G[d1*256 + t] = acc;
}
/* P[h*128+d][d2] = sum_e Wv[d][h*128+e] * Wfc[h*128+e][d2] */
__global__ void k_precomp_P(const float* __restrict__ Wv, const float* __restrict__ Wfc) {
    int hd = blockIdx.x, d2 = threadIdx.x;
    int h = hd >> 7, d = hd & 127;
    float acc = 0.f;
    const float* wv = Wv + d*256 + h*128;
    const float* wf = Wfc + (h*128)*128 + d2;
    for (int e = 0; e < 128; e++) acc += wv[e] * wf[e*128];
    g_P[hd*128 + d2] = acc;
}
/* w_{src,dst}[L][s][h][d] = sum_e W[L,h,d,e] * a[L,h,e] */
__global__ void k_precomp_gat(const float* __restrict__ W, const float* __restrict__ asrc,
                              const float* __restrict__ adst) {
    int bi = blockIdx.x, d = threadIdx.x;           /* bi = L*4 + s*2 + h */
    int L = bi >> 2, s = (bi >> 1) & 1, h = bi & 1;
    const float* a = (s ? adst : asrc) + (L*2 + h)*128;
    const float* wr = W + (long)((L*2 + h)*128 + d)*128;
    float acc = 0.f;
    for (int e = 0; e < 128; e++) acc += wr[e] * a[e];
    g_wsd[bi*128 + d] = acc;
}
__global__ void k_transW(const float* __restrict__ W) {
    int j = blockIdx.y, dd = blockIdx.x, e = threadIdx.x;
    g_Wt[j*DD*DD + dd*DD + e] = W[j*DD*DD + e*DD + dd];
}

/* ------------------------- SGEMM (R1-proven FFMA 8x8), z-selects B/C ---------- */
__global__ __launch_bounds__(256, 2)
void k_gemm(const float* __restrict__ A, int lda,
            const float* __restrict__ B0, const float* __restrict__ B1, int ldb,
            float* __restrict__ C0, float* __restrict__ C1,
            int ldc, int M, int K) {
    const int BK = 16;
    __shared__ float As[BK][128 + 4];
    __shared__ float Bs[BK][128 + 4];
    const float* B = blockIdx.z ? B1 : B0;
    float* C = blockIdx.z ? C1 : C0;
    int tid = threadIdx.x;
    int bm = blockIdx.y * 128, bn = blockIdx.x * 128;
    int tx = tid & 15, ty = tid >> 4;
    float acc[8][8];
#pragma unroll
    for (int i = 0; i < 8; i++)
#pragma unroll
        for (int j = 0; j < 8; j++) acc[i][j] = 0.f;

    for (int k0 = 0; k0 < K; k0 += BK) {
#pragma unroll
        for (int i = 0; i < 2; i++) {
            int lin = tid + i*256;
            int r = lin >> 2, c = (lin & 3) << 2;
            float4 av = make_float4(0.f, 0.f, 0.f, 0.f);
            if (bm + r < M) av = *(const float4*)(A + (long)(bm+r)*lda + k0 + c);
            As[c  ][r] = av.x; As[c+1][r] = av.y; As[c+2][r] = av.z; As[c+3][r] = av.w;
        }
#pragma unroll
        for (int i = 0; i < 2; i++) {
            int lin = tid + i*256;
            int r = lin >> 5, c = (lin & 31) << 2;
            *(float4*)&Bs[r][c] = *(const float4*)(B + (long)(k0+r)*ldb + bn + c);
        }
        __syncthreads();
#pragma unroll
        for (int kk = 0; kk < BK; kk++) {
            float a[8], bb[8];
            *(float4*)&a[0]  = *(const float4*)&As[kk][ty*8];
            *(float4*)&a[4]  = *(const float4*)&As[kk][ty*8 + 4];
            *(float4*)&bb[0] = *(const float4*)&Bs[kk][tx*8];
            *(float4*)&bb[4] = *(const float4*)&Bs[kk][tx*8 + 4];
#pragma unroll
            for (int i = 0; i < 8; i++)
#pragma unroll
                for (int j = 0; j < 8; j++) acc[i][j] += a[i] * bb[j];
        }
        __syncthreads();
    }
#pragma unroll
    for (int i = 0; i < 8; i++) {
        int r = bm + ty*8 + i;
        if (r < M) {
#pragma unroll
            for (int j = 0; j < 8; j += 4) {
                float4 cv = make_float4(acc[i][j], acc[i][j+1], acc[i][j+2], acc[i][j+3]);
                *(float4*)(C + (long)r*ldc + bn + tx*8 + j) = cv;
            }
        }
    }
}

/* ------------------------- GAT: es/ed dots on raw x (warp/row) ---------------- */
__global__ __launch_bounds__(256) void k_esed(int L) {
    int w = blockIdx.x*8 + (threadIdx.x >> 5);
    if (w >= NB) return;
    int lane = threadIdx.x & 31;
    float4 x4 = *(const float4*)(g_seq + (long)w*384 + L*128 + lane*4);
    const float* base = g_wsd + L*512;
    float4 ws0 = *(const float4*)(base       + lane*4);
    float4 ws1 = *(const float4*)(base + 128 + lane*4);
    float4 wd0 = *(const float4*)(base + 256 + lane*4);
    float4 wd1 = *(const float4*)(base + 384 + lane*4);
    float v0 = wrsum(dot4(x4, ws0));
    float v1 = wrsum(dot4(x4, wd0));
    float v2 = wrsum(dot4(x4, ws1));
    float v3 = wrsum(dot4(x4, wd1));
    if (lane == 0) { g_es0[w] = v0; g_ed0[w] = v1; g_es1[w] = v2; g_ed1[w] = v3; }
}

/* ------------------------- GAT: softmax-mix in x-space (warp/row) -------------
   0.5 head-mean folded into the softmax normalizers. ---------------------------*/
__global__ __launch_bounds__(256) void k_gat_mix(int L) {
    int w = blockIdx.x*8 + (threadIdx.x >> 5);
    if (w >= NB) return;
    int lane = threadIdx.x & 31;
    int b = w / NN;
    int deg = g_adj_deg[w];
    const int* cols = g_adj_cols + (long)w * MAXDEG;
    int creg[4]; float e0r[4], e1r[4];
    float es0 = g_es0[w], es1 = g_es1[w];
    float m0 = -1e30f, m1 = -1e30f;
#pragma unroll
    for (int i = 0; i < 4; i++) {
        int j = i*32 + lane;
        creg[i] = 0; e0r[i] = -1e30f; e1r[i] = -1e30f;
        if (j < deg) {
            int c = cols[j]; creg[i] = c;
            float t0 = es0 + g_ed0[b*NN + c]; e0r[i] = (t0 > 0.f) ? t0 : 0.2f*t0;
            float t1 = es1 + g_ed1[b*NN + c]; e1r[i] = (t1 > 0.f) ? t1 : 0.2f*t1;
            m0 = fmaxf(m0, e0r[i]); m1 = fmaxf(m1, e1r[i]);
        }
    }
    m0 = wrmax(m0); m1 = wrmax(m1);
    float s0 = 0.f, s1 = 0.f;
    float p0r[4], p1r[4];
#pragma unroll
    for (int i = 0; i < 4; i++) {
        int j = i*32 + lane;
        p0r[i] = (j < deg) ? expf(e0r[i] - m0) : 0.f;
        p1r[i] = (j < deg) ? expf(e1r[i] - m1) : 0.f;
        s0 += p0r[i]; s1 += p1r[i];
    }
    s0 = wrsum(s0); s1 = wrsum(s1);
    float inv0 = 0.5f / s0, inv1 = 0.5f / s1;   /* fold head-mean */
    float4 a0 = make_float4(0.f, 0.f, 0.f, 0.f);
    float4 a1 = make_float4(0.f, 0.f, 0.f, 0.f);
    for (int i = 0; i < 4 && i*32 < deg; i++) {
        for (int l = 0; l < 32; l++) {
            int j = i*32 + l;
            if (j >= deg) break;                    /* uniform across warp */
            int   c  = __shfl_sync(0xffffffffu, creg[i], l);
            float w0 = __shfl_sync(0xffffffffu, p0r[i], l) * inv0;
            float w1 = __shfl_sync(0xffffffffu, p1r[i], l) * inv1;
            float4 x4 = *(const float4*)(g_seq + (long)(b*NN + c)*384 + L*128 + lane*4);
            a0.x += w0*x4.x; a0.y += w0*x4.y; a0.z += w0*x4.z; a0.w += w0*x4.w;
            a1.x += w1*x4.x; a1.y += w1*x4.y; a1.z += w1*x4.z; a1.w += w1*x4.w;
        }
    }
    *(float4*)(g_mix + (long)w*256       + lane*4) = a0;
    *(float4*)(g_mix + (long)w*256 + 128 + lane*4) = a1;
}

/* ------------------------- GAT: elu + normalize -> seq slot ------------------- */
__global__ __launch_bounds__(256) void k_gat_post(int lslot) {
    int w = blockIdx.x*8 + (threadIdx.x >> 5);
    if (w >= NB) return;
    int lane = threadIdx.x & 31;
    float4 mv = *(const float4*)(g_mv + (long)w*DD + lane*4);
    float4 ev;
    ev.x = (mv.x > 0.f) ? mv.x : expm1f(mv.x);
    ev.y = (mv.y > 0.f) ? mv.y : expm1f(mv.y);
    ev.z = (mv.z > 0.f) ? mv.z : expm1f(mv.z);
    ev.w = (mv.w > 0.f) ? mv.w : expm1f(mv.w);
    float ss = wrsum(dot4(ev, ev));
    float nrm = 1.f / fmaxf(sqrtf(ss), 1e-12f);
    *(float4*)(g_seq + ((long)w*3 + lslot)*DD + lane*4) =
        make_float4(ev.x*nrm, ev.y*nrm, ev.z*nrm, ev.w*nrm);
}

/* ------------------------- MHA: scores via y.x, mix x (warp/node) ------------- */
__global__ __launch_bounds__(256) void k_mha() {
    int w = blockIdx.x*8 + (threadIdx.x >> 5);
    if (w >= NB) return;
    int lane = threadIdx.x & 31;
    float4 x4[3], y4[3][2];
#pragma unroll
    for (int l = 0; l < 3; l++) {
        x4[l] = *(const float4*)(g_seq + (long)w*384 + l*128 + lane*4);
#pragma unroll
        for (int h = 0; h < 2; h++)
            y4[l][h] = *(const float4*)(g_y2 + (long)w*768 + l*256 + h*128 + lane*4);
    }
    float sc[2][3][3];
#pragma unroll
    for (int h = 0; h < 2; h++)
#pragma unroll
        for (int l = 0; l < 3; l++)
#pragma unroll
            for (int m = 0; m < 3; m++)
                sc[h][l][m] = wrsum(dot4(y4[l][h], x4[m])) * 0.08838834764831845f;
#pragma unroll
    for (int h = 0; h < 2; h++)
#pragma unroll
        for (int l = 0; l < 3; l++) {
            float a0 = sc[h][l][0], a1 = sc[h][l][1], a2 = sc[h][l][2];
            float m = fmaxf(a0, fmaxf(a1, a2));
            float e0 = expf(a0 - m), e1 = expf(a1 - m), e2 = expf(a2 - m);
            float inv = 1.f / (e0 + e1 + e2);
            e0 *= inv; e1 *= inv; e2 *= inv;
            float4 z;
            z.x = e0*x4[0].x + e1*x4[1].x + e2*x4[2].x;
            z.y = e0*x4[0].y + e1*x4[1].y + e2*x4[2].y;
            z.z = e0*x4[0].z + e1*x4[1].z + e2*x4[2].z;
            z.w = e0*x4[0].w + e1*x4[1].w + e2*x4[2].w;
            *(float4*)(g_z + (long)w*768 + l*256 + h*128 + lane*4) = z;
        }
}

/* ------------------------- residual + LN + mean (warp/row) -------------------- */
__global__ __launch_bounds__(256) void k_ln(const float* __restrict__ g,
                                            const float* __restrict__ bb,
                                            float* __restrict__ out) {
    int w = blockIdx.x*8 + (threadIdx.x >> 5);
    if (w >= NB) return;
    int lane = threadIdx.x & 31;
    int b = w / NN, row = w - b*NN;
    float4 g4 = *(const float4*)(g + lane*4);
    float4 b4 = *(const float4*)(bb + lane*4);
    float4 acc = make_float4(0.f, 0.f, 0.f, 0.f);
#pragma unroll
    for (int l = 0; l < 3; l++) {
        float4 v0 = *(const float4*)(g_of + ((long)w*3 + l)*DD + lane*4);
        float4 v1 = *(const float4*)(g_seq + ((long)w*3 + l)*DD + lane*4);
        float4 v = make_float4(v0.x+v1.x, v0.y+v1.y, v0.z+v1.z, v0.w+v1.w);
        float s  = wrsum(v.x + v.y + v.z + v.w);
        float s2 = wrsum(dot4(v, v));
        float mu  = s * (1.f/128.f);
        float var = s2 * (1.f/128.f) - mu*mu;
        float is = rsqrtf(var + 1e-6f);
        acc.x += g4.x*(v.x - mu)*is + b4.x;
        acc.y += g4.y*(v.y - mu)*is + b4.y;
        acc.z += g4.z*(v.z - mu)*is + b4.z;
        acc.w += g4.w*(v.w - mu)*is + b4.w;
    }
    float4 r = make_float4(acc.x*(1.f/3.f), acc.y*(1.f/3.f),
                           acc.z*(1.f/3.f), acc.w*(1.f/3.f));
    *(float4*)(out + (long)b*NN*256 + (long)row*256 + lane*4) = r;
}

/* ------------------------- HGC pieces (warp/row) ------------------------------ */
__global__ __launch_bounds__(256) void k_u0(const float* __restrict__ e0,
                                            const float* __restrict__ e1) {
    int w = blockIdx.x*8 + (threadIdx.x >> 5);
    if (w >= NB) return;
    int lane = threadIdx.x & 31;
    int b = w / NN, row = w - b*NN;
    float4 x = *(const float4*)((b ? e1 : e0) + (long)row*DD + lane*4);
    float s = wrsum(dot4(x, x));
    float n0 = fmaxf(sqrtf(s), 1e-15f);
    float ne = tanhf(n0);
    float pe = (ne > MAXN_) ? MAXN_/ne : 1.f;
    float np = fmaxf(ne*pe, 1e-15f);
    float c  = atanhf(fminf(np, 1.f - 1e-7f)) / np * (ne / n0) * pe;
    *(float4*)(g_u + (long)w*DD + lane*4) =
        make_float4(c*x.x, c*x.y, c*x.z, c*x.w);
}

__global__ __launch_bounds__(256) void k_hgc_bias(const float* __restrict__ T,
                                                  const float* __restrict__ bvec,
                                                  float* __restrict__ Y) {
    int w = blockIdx.x*8 + (threadIdx.x >> 5);
    if (w >= NB) return;
    int lane = threadIdx.x & 31;
    float4 t4 = *(const float4*)(T + (long)w*DD + lane*4);
    float4 b4 = *(const float4*)(bvec + lane*4);
    float s0 = wrsum(dot4(t4, t4));
    float s1 = wrsum(dot4(b4, b4));
    float s2 = wrsum(dot4(t4, b4));
    float nt = fmaxf(sqrtf(s0), 1e-15f);
    float et = tanhf(nt);
    float pt = (et > MAXN_) ? MAXN_/et : 1.f;
    float cm = (et/nt) * pt;
    float x2 = (et*pt) * (et*pt);
    float nb = fmaxf(sqrtf(s1), 1e-15f);
    float eb = tanhf(nb);
    float pb = (eb > MAXN_) ? MAXN_/eb : 1.f;
    float cb = (eb/nb) * pb;
    float y2 = (eb*pb) * (eb*pb);
    float xy = cm * cb * s2;
    float den = fmaxf(1.f + 2.f*xy + x2*y2, 1e-15f);
    float fA = (1.f + 2.f*xy + y2) * cm / den;
    float fB = (1.f - x2) * cb / den;
    float4 r = make_float4(fA*t4.x + fB*b4.x, fA*t4.y + fB*b4.y,
                           fA*t4.z + fB*b4.z, fA*t4.w + fB*b4.w);
    float s3 = wrsum(dot4(r, r));
    float nr = fmaxf(sqrtf(s3), 1e-15f);
    float pr = (nr > MAXN_) ? MAXN_/nr : 1.f;
    float np = fmaxf(nr*pr, 1e-15f);
    float c2 = atanhf(fminf(np, 1.f - 1e-7f)) / np * pr;
    *(float4*)(Y + (long)w*DD + lane*4) =
        make_float4(c2*r.x, c2*r.y, c2*r.z, c2*r.w);
}

__global__ __launch_bounds__(256) void k_hgc_agg(const float* __restrict__ Y,
                                                 float* __restrict__ W) {
    int w = blockIdx.x*8 + (threadIdx.x >> 5);
    if (w >= NB) return;
    int lane = threadIdx.x & 31;
    int b = w / NN;
    const int* cols = g_adj_cols + (long)w * MAXDEG;
    int deg = g_adj_deg[w];
    float4 acc = make_float4(0.f, 0.f, 0.f, 0.f);
    for (int j = 0; j < deg; j++) {
        int c = __ldg(&cols[j]);
        float4 v = *(const float4*)(Y + (long)(b*NN + c)*DD + lane*4);
        acc.x += v.x; acc.y += v.y; acc.z += v.z; acc.w += v.w;
    }
    float inv = 1.f / (float)deg;
    float4 z = make_float4(acc.x*inv, acc.y*inv, acc.z*inv, acc.w*inv);
    float4 rz = make_float4(fmaxf(z.x, 0.f), fmaxf(z.y, 0.f),
                            fmaxf(z.z, 0.f), fmaxf(z.w, 0.f));
    float s0 = wrsum(dot4(z, z));
    float s1 = wrsum(dot4(rz, rz));
    float nz = fmaxf(sqrtf(s0), 1e-15f);
    float e1 = tanhf(nz);
    float p1 = (e1 > MAXN_) ? MAXN_/e1 : 1.f;
    float cH = (e1/nz) * p1;
    float nH = fmaxf(e1*p1, 1e-15f);
    float cT = atanhf(fminf(nH, 1.f - 1e-7f)) / nH * cH;
    float nt2 = fmaxf(cT * sqrtf(s1), 1e-15f);
    float e2 = tanhf(nt2);
    float p2 = (e2 > MAXN_) ? MAXN_/e2 : 1.f;
    float hcoef = (e2/nt2) * p2 * cT;
    float nH2 = fmaxf(e2*p2, 1e-15f);
    float c2 = atanhf(fminf(nH2, 1.f - 1e-7f)) / nH2;
    float cc = c2 * hcoef;
    *(float4*)(W + (long)w*DD + lane*4) =
        make_float4(cc*rz.x, cc*rz.y, cc*rz.z, cc*rz.w);
}

__global__ __launch_bounds__(256) void k_hs(const float* __restrict__ e0,
                                            const float* __restrict__ e1,
                                            float* __restrict__ out) {
    int w = blockIdx.x*8 + (threadIdx.x >> 5);
    if (w >= NB) return;
    int lane = threadIdx.x & 31;
    int b = w / NN, row = w - b*NN;
    float4 e = *(const float4*)((b ? e1 : e0) + (long)row*DD + lane*4);
    float4 v = *(const float4*)(g_w2 + (long)w*DD + lane*4);
    *(float4*)(out + (long)(2+b)*NN*256 + (long)row*256 + lane*4) =
        make_float4(e.x+v.x, e.y+v.y, e.z+v.z, e.w+v.w);
}

/* ------------------------- host driver ----------------------------------------- */
extern "C" void kernel_launch(void* const* d_in, const int* in_sizes, int n_in,
                              void* d_out, int out_size) {
    const float* ent_sr    = (const float*)d_in[0];
    const float* ent_tg    = (const float*)d_in[1];
    const float* rel_sr    = (const float*)d_in[2];
    const float* rel_tg    = (const float*)d_in[3];
    const float* adj_sr    = (const float*)d_in[4];
    const float* adj_tg    = (const float*)d_in[5];
    const float* rel_adj_sr= (const float*)d_in[6];
    const float* rel_adj_tg= (const float*)d_in[7];
    const float* gat_W     = (const float*)d_in[8];
    const float* gat_a_src = (const float*)d_in[9];
    const float* gat_a_dst = (const float*)d_in[10];
    const float* Wq        = (const float*)d_in[11];
    const float* Wk        = (const float*)d_in[12];
    const float* Wv        = (const float*)d_in[13];
    const float* Wfc       = (const float*)d_in[14];
    const float* ln_g      = (const float*)d_in[15];
    const float* ln_b      = (const float*)d_in[16];
    const float* hgc_W     = (const float*)d_in[17];
    const float* hgc_b     = (const float*)d_in[18];
    float* out = (float*)d_out;

    float *seq, *mix, *mv, *y2, *z, *of, *u, *t, *y, *w, *w2, *Wt, *G, *P;
    cudaGetSymbolAddress((void**)&seq, g_seq);
    cudaGetSymbolAddress((void**)&mix, g_mix);
    cudaGetSymbolAddress((void**)&mv,  g_mv);
    cudaGetSymbolAddress((void**)&y2,  g_y2);
    cudaGetSymbolAddress((void**)&z,   g_z);
    cudaGetSymbolAddress((void**)&of,  g_of);
    cudaGetSymbolAddress((void**)&u,   g_u);
    cudaGetSymbolAddress((void**)&t,   g_t);
    cudaGetSymbolAddress((void**)&y,   g_y);
    cudaGetSymbolAddress((void**)&w,   g_w);
    cudaGetSymbolAddress((void**)&w2,  g_w2);
    cudaGetSymbolAddress((void**)&Wt,  g_Wt);
    cudaGetSymbolAddress((void**)&G,   g_G);
    cudaGetSymbolAddress((void**)&P,   g_P);

    dim3 gGAT(1, (12000 + 127) / 128, 1);    /* [12000,256]@[256,128] */
    dim3 gY  (2, (36000 + 127) / 128, 1);    /* [36000,128]@[128,256] */
    dim3 gOF (1, (36000 + 127) / 128, 1);    /* [36000,256]@[256,128] */
    dim3 gHGC(1, (12000 + 127) / 128, 1);

    /* sparsify + precompute */
    k_build_adj<<<dim3(NN, 2), 256>>>(adj_sr, adj_tg);
    k_build_rel<<<dim3(NN, 2), 256>>>(rel_adj_sr, rel_adj_tg);
    k_relagg<<<NWB, 256>>>(rel_sr, rel_tg, out);
    k_seq0<<<NWB, 256>>>(ent_sr, ent_tg);
    k_precomp_G<<<128, 256>>>(Wq, Wk);
    k_precomp_P<<<256, 128>>>(Wv, Wfc);
    k_precomp_gat<<<8, 128>>>(gat_W, gat_a_src, gat_a_dst);
    k_transW<<<dim3(DD, 2), DD>>>(hgc_W);

    /* GAT x2: attention on raw x, mix in x-space, one GEMM (B = raw gat_W), post */
    for (int L = 0; L < 2; L++) {
        k_esed<<<NWB, 256>>>(L);
        k_gat_mix<<<NWB, 256>>>(L);
        k_gemm<<<gGAT, 256>>>(mix, 256, gat_W + (long)L*256*128, gat_W, 128,
                              mv, mv, 128, 12000, 256);
        k_gat_post<<<NWB, 256>>>(L + 1);
    }

    /* MHA: y = x@G, per-node attention+mix, of = z@P */
    k_gemm<<<gY, 256>>>(seq, 128, G, G, 256, y2, y2, 256, 36000, 128);
    k_mha<<<NWB, 256>>>();
    k_gemm<<<gOF, 256>>>(z, 256, P, P, 128, of, of, 128, 36000, 256);
    k_ln<<<NWB, 256>>>(ln_g, ln_b, out);

    /* HGC encoder */
    k_u0<<<NWB, 256>>>(ent_sr, ent_tg);
    k_gemm<<<gHGC, 256>>>(u, 128, Wt, Wt, 128, t, t, 128, 12000, 128);
    k_hgc_bias<<<NWB, 256>>>(t, hgc_b, y);
    k_hgc_agg<<<NWB, 256>>>(y, w);
    k_gemm<<<gHGC, 256>>>(w, 128, Wt + DD*DD, Wt + DD*DD, 128, t, t, 128, 12000, 128);
    k_hgc_bias<<<NWB, 256>>>(t, hgc_b + DD, y);
    k_hgc_agg<<<NWB, 256>>>(y, w2);
    k_hs<<<NWB, 256>>>(ent_sr, ent_tg, out);
}

// round 8
// speedup vs baseline: 2.2350x; 1.2841x over previous
#include <cuda_runtime.h>
#include <cuda_bf16.h>
#include <math.h>
#include <stdint.h>

#define NN      6000
#define DD      128
#define RR      1000
#define MAXDEG  128
#define MAXRDEG 64
#define NB      12000     /* 2*NN: both branches stacked */
#define NWB     1500      /* NB/8 warp-per-row grid */
#define MAXN_   0.996f    /* 1 - 4e-3 */

/* ------------------------- static scratch (no allocs) ------------------------- */
__device__ __align__(16) float g_seq[(long)NB*3*DD];       /* [n][l][d] */
__device__ __align__(16) float g_mix[(long)NB*2*DD];       /* [n][h*128+d] x-space mixed */
__device__ __align__(16) float g_mv [(long)NB*DD];         /* GAT layer pre-activation */
__device__ float g_es0[NB], g_ed0[NB], g_es1[NB], g_ed1[NB];
__device__ __align__(16) float g_y2[(long)NB*3*2*DD];      /* y = x @ G */
__device__ __align__(16) float g_z [(long)NB*3*2*DD];      /* attn-mixed x, per head */
__device__ __align__(16) float g_of[(long)NB*3*DD];
__device__ __align__(16) float g_u [(long)NB*DD];
__device__ __align__(16) float g_t [(long)NB*DD];
__device__ __align__(16) float g_y [(long)NB*DD];
__device__ __align__(16) float g_w [(long)NB*DD];
__device__ __align__(16) float g_w2[(long)NB*DD];
__device__ __align__(16) float g_Gt [2*DD*DD];             /* [t=h*128+d2][d1] */
__device__ __align__(16) float g_Pt [DD*2*DD];             /* [d2][hd] */
__device__ __align__(16) float g_Wgt[2*DD*2*DD];           /* [L][e][h*128+d] */
__device__ __align__(16) float g_wsd[2*2*2*DD];            /* [L][s][h][d] */
__device__ int g_adj_cols[(long)NB*MAXDEG];
__device__ int g_adj_deg[NB];
__device__ int g_rel_cols[(long)NB*MAXRDEG];
__device__ int g_rel_deg[NB];

/* ------------------------- warp helpers --------------------------------------- */
__device__ __forceinline__ float wrsum(float x) {
#pragma unroll
    for (int o = 16; o; o >>= 1) x += __shfl_xor_sync(0xffffffffu, x, o);
    return x;
}
__device__ __forceinline__ float wrmax(float x) {
#pragma unroll
    for (int o = 16; o; o >>= 1) x = fmaxf(x, __shfl_xor_sync(0xffffffffu, x, o));
    return x;
}
__device__ __forceinline__ float dot4(float4 a, float4 b) {
    return a.x*b.x + a.y*b.y + a.z*b.z + a.w*b.w;
}

/* ------------------------- CSR builders --------------------------------------- */
__global__ void k_build_adj(const float* __restrict__ a0, const float* __restrict__ a1) {
    int row = blockIdx.x, b = blockIdx.y;
    const float4* adj = (const float4*)((b ? a1 : a0) + (long)row * NN);
    __shared__ int cnt;
    if (threadIdx.x == 0) cnt = 0;
    __syncthreads();
    int* mc = g_adj_cols + (long)(b*NN + row) * MAXDEG;
    for (int c = threadIdx.x; c < NN/4; c += blockDim.x) {
        float4 v = adj[c];
        if (v.x > 0.f) { int p = atomicAdd(&cnt, 1); if (p < MAXDEG) mc[p] = c*4;   }
        if (v.y > 0.f) { int p = atomicAdd(&cnt, 1); if (p < MAXDEG) mc[p] = c*4+1; }
        if (v.z > 0.f) { int p = atomicAdd(&cnt, 1); if (p < MAXDEG) mc[p] = c*4+2; }
        if (v.w > 0.f) { int p = atomicAdd(&cnt, 1); if (p < MAXDEG) mc[p] = c*4+3; }
    }
    __syncthreads();
    if (threadIdx.x == 0) g_adj_deg[b*NN + row] = min(cnt, MAXDEG);
}
__global__ void k_build_rel(const float* __restrict__ a0, const float* __restrict__ a1) {
    int row = blockIdx.x, b = blockIdx.y;
    const float4* adj = (const float4*)((b ? a1 : a0) + (long)row * RR);
    __shared__ int cnt;
    if (threadIdx.x == 0) cnt = 0;
    __syncthreads();
    int* mc = g_rel_cols + (long)(b*NN + row) * MAXRDEG;
    for (int c = threadIdx.x; c < RR/4; c += blockDim.x) {
        float4 v = adj[c];
        if (v.x > 0.f) { int p = atomicAdd(&cnt, 1); if (p < MAXRDEG) mc[p] = c*4;   }
        if (v.y > 0.f) { int p = atomicAdd(&cnt, 1); if (p < MAXRDEG) mc[p] = c*4+1; }
        if (v.z > 0.f) { int p = atomicAdd(&cnt, 1); if (p < MAXRDEG) mc[p] = c*4+2; }
        if (v.w > 0.f) { int p = atomicAdd(&cnt, 1); if (p < MAXRDEG) mc[p] = c*4+3; }
    }
    __syncthreads();
    if (threadIdx.x == 0) g_rel_deg[b*NN + row] = min(cnt, MAXRDEG);
}

/* ------------------------- rel aggregator (warp/row) -------------------------- */
__global__ __launch_bounds__(256) void k_relagg(const float* __restrict__ r0,
                                                const float* __restrict__ r1,
                                                float* __restrict__ out) {
    int w = blockIdx.x*8 + (threadIdx.x >> 5);
    if (w >= NB) return;
    int lane = threadIdx.x & 31;
    int b = w / NN, row = w - b*NN;
    const float* remb = b ? r1 : r0;
    const int* cols = g_rel_cols + (long)w * MAXRDEG;
    int deg = g_rel_deg[w];
    float4 acc = make_float4(0.f, 0.f, 0.f, 0.f);
    for (int j = 0; j < deg; j++) {
        int c = __ldg(&cols[j]);
        float4 v = *(const float4*)(remb + (long)c*DD + lane*4);
        acc.x += v.x; acc.y += v.y; acc.z += v.z; acc.w += v.w;
    }
    float inv = 1.f / (float)deg;
    float4 r = make_float4(acc.x*inv, acc.y*inv, acc.z*inv, acc.w*inv);
    *(float4*)(out + (long)b*NN*256 + (long)row*256 + 128 + lane*4) = r;
    *(float4*)(out + (long)(2+b)*NN*256 + (long)row*256 + 128 + lane*4) = r;
}

/* ------------------------- seq slot-0 copy ------------------------------------ */
__global__ __launch_bounds__(256) void k_seq0(const float* __restrict__ e0,
                                              const float* __restrict__ e1) {
    int idx = blockIdx.x*256 + threadIdx.x;       /* over NB*32 float4 */
    if (idx >= NB*32) return;
    int n = idx >> 5, c = idx & 31;
    int b = n / NN, row = n - b*NN;
    const float4* src = (const float4*)((b ? e1 : e0) + (long)row*DD);
    ((float4*)(g_seq + (long)n*384))[c] = src[c];
}

/* ------------------------- precompute kernels --------------------------------- */
/* Gt[t=h*128+d2][d1] = sum_e Wq[d1][h*128+e] * Wk[d2][h*128+e] */
__global__ void k_precomp_Gt(const float* __restrict__ Wq, const float* __restrict__ Wk) {
    int t = blockIdx.x, d1 = threadIdx.x;
    int h = t >> 7, d2 = t & 127;
    const float* wq = Wq + d1*256 + h*128;
    const float* wk = Wk + d2*256 + h*128;
    float acc = 0.f;
    for (int e = 0; e < 128; e++) acc += wq[e] * wk[e];
    g_Gt[t*128 + d1] = acc;
}
/* Pt[d2][hd] = sum_e Wv[d][h*128+e] * Wfc[h*128+e][d2] */
__global__ void k_precomp_Pt(const float* __restrict__ Wv, const float* __restrict__ Wfc) {
    int hd = blockIdx.x, d2 = threadIdx.x;
    int h = hd >> 7, d = hd & 127;
    const float* wv = Wv + d*256 + h*128;
    const float* wf = Wfc + (h*128)*128 + d2;
    float acc = 0.f;
    for (int e = 0; e < 128; e++) acc += wv[e] * wf[e*128];
    g_Pt[d2*256 + hd] = acc;
}
/* w_{src,dst}[L][s][h][d] = sum_e W[L,h,d,e] * a[L,h,e] */
__global__ void k_precomp_gat(const float* __restrict__ W, const float* __restrict__ asrc,
                              const float* __restrict__ adst) {
    int bi = blockIdx.x, d = threadIdx.x;           /* bi = L*4 + s*2 + h */
    int L = bi >> 2, s = (bi >> 1) & 1, h = bi & 1;
    const float* a = (s ? adst : asrc) + (L*2 + h)*128;
    const float* wr = W + (long)((L*2 + h)*128 + d)*128;
    float acc = 0.f;
    for (int e = 0; e < 128; e++) acc += wr[e] * a[e];
    g_wsd[bi*128 + d] = acc;
}
/* Wgt[L][e][h*128+d] = gat_W[L][h][d][e] */
__global__ void k_precomp_Wgt(const float* __restrict__ W) {
    int idx = blockIdx.x*256 + threadIdx.x;        /* 2*2*128*128 */
    if (idx >= 2*2*DD*DD) return;
    int e = idx & 127, d = (idx >> 7) & 127, h = (idx >> 14) & 1, L = idx >> 15;
    g_Wgt[((long)L*128 + e)*256 + h*128 + d] = W[idx];
}

/* ------------------------- bf16-split HMMA GEMM -------------------------------
   C[M,N] = A[M,K] @ Bt[N,K]^T, fp32 in/out, 3-pass bf16 hi/lo split via
   mma.sync.m16n8k16 (base-target PTX; no sm_103a features).
   128x128 tile, 256 thr = 8 warps (4x2), warp = 32x64 (2 mt x 8 nt).    ------ */
#define SLDA 40   /* smem row stride in halfs (32 + 8 pad) */

__device__ __forceinline__ void mma_bf16(float* d, const uint32_t* a,
                                         const uint32_t* b) {
    asm volatile(
        "mma.sync.aligned.m16n8k16.row.col.f32.bf16.bf16.f32 "
        "{%0,%1,%2,%3}, {%4,%5,%6,%7}, {%8,%9}, {%0,%1,%2,%3};"
        : "+f"(d[0]), "+f"(d[1]), "+f"(d[2]), "+f"(d[3])
        : "r"(a[0]), "r"(a[1]), "r"(a[2]), "r"(a[3]), "r"(b[0]), "r"(b[1]));
}

__global__ void __launch_bounds__(256, 1)
k_hmma(const float* __restrict__ A, int lda,
       const float* __restrict__ Bt, int ldb,
       float* __restrict__ C, int ldc, int M, int K) {
    __shared__ __nv_bfloat16 sAh[128*SLDA], sAl[128*SLDA];
    __shared__ __nv_bfloat16 sBh[128*SLDA], sBl[128*SLDA];
    int tid = threadIdx.x, wid = tid >> 5, lane = tid & 31;
    int wm = wid & 3, wn = wid >> 2;          /* 4 x 2 warp grid */
    int g = lane >> 2, tg = lane & 3;
    int bm = blockIdx.y * 128, bn = blockIdx.x * 128;

    float acc[2][8][4];
#pragma unroll
    for (int i = 0; i < 2; i++)
#pragma unroll
        for (int j = 0; j < 8; j++)
#pragma unroll
            for (int r = 0; r < 4; r++) acc[i][j][r] = 0.f;

    for (int kc = 0; kc < K; kc += 32) {
        /* stage + split: A tile 128x32, B tile 128x32 (rows = N of Bt) */
#pragma unroll
        for (int it = 0; it < 4; it++) {
            int idx = tid + it*256;            /* 1024 float4 slots */
            int r = idx >> 3, c4 = (idx & 7) << 2;
            float4 va = make_float4(0.f, 0.f, 0.f, 0.f);
            if (bm + r < M) va = *(const float4*)(A + (long)(bm+r)*lda + kc + c4);
            __nv_bfloat162 h0 = __float22bfloat162_rn(make_float2(va.x, va.y));
            __nv_bfloat162 h1 = __float22bfloat162_rn(make_float2(va.z, va.w));
            float2 f0 = __bfloat1622float2(h0), f1 = __bfloat1622float2(h1);
            __nv_bfloat162 l0 = __float22bfloat162_rn(make_float2(va.x-f0.x, va.y-f0.y));
            __nv_bfloat162 l1 = __float22bfloat162_rn(make_float2(va.z-f1.x, va.w-f1.y));
            *(uint2*)&sAh[r*SLDA + c4] = make_uint2(*(uint32_t*)&h0, *(uint32_t*)&h1);
            *(uint2*)&sAl[r*SLDA + c4] = make_uint2(*(uint32_t*)&l0, *(uint32_t*)&l1);

            float4 vb = *(const float4*)(Bt + (long)(bn+r)*ldb + kc + c4);
            h0 = __float22bfloat162_rn(make_float2(vb.x, vb.y));
            h1 = __float22bfloat162_rn(make_float2(vb.z, vb.w));
            f0 = __bfloat1622float2(h0); f1 = __bfloat1622float2(h1);
            l0 = __float22bfloat162_rn(make_float2(vb.x-f0.x, vb.y-f0.y));
            l1 = __float22bfloat162_rn(make_float2(vb.z-f1.x, vb.w-f1.y));
            *(uint2*)&sBh[r*SLDA + c4] = make_uint2(*(uint32_t*)&h0, *(uint32_t*)&h1);
            *(uint2*)&sBl[r*SLDA + c4] = make_uint2(*(uint32_t*)&l0, *(uint32_t*)&l1);
        }
        __syncthreads();

#pragma unroll
        for (int ks = 0; ks < 32; ks += 16) {
            uint32_t ah[2][4], al[2][4];
#pragma unroll
            for (int mt = 0; mt < 2; mt++) {
                int r0 = (wm*32 + mt*16 + g) * SLDA + ks + tg*2;
                int r8 = r0 + 8*SLDA;
                ah[mt][0] = *(const uint32_t*)&sAh[r0];
                ah[mt][1] = *(const uint32_t*)&sAh[r8];
                ah[mt][2] = *(const uint32_t*)&sAh[r0 + 8];
                ah[mt][3] = *(const uint32_t*)&sAh[r8 + 8];
                al[mt][0] = *(const uint32_t*)&sAl[r0];
                al[mt][1] = *(const uint32_t*)&sAl[r8];
                al[mt][2] = *(const uint32_t*)&sAl[r0 + 8];
                al[mt][3] = *(const uint32_t*)&sAl[r8 + 8];
            }
#pragma unroll
            for (int nt = 0; nt < 8; nt++) {
                int n0 = (wn*64 + nt*8 + g) * SLDA + ks + tg*2;
                uint32_t bh[2], bl[2];
                bh[0] = *(const uint32_t*)&sBh[n0];
                bh[1] = *(const uint32_t*)&sBh[n0 + 8];
                bl[0] = *(const uint32_t*)&sBl[n0];
                bl[1] = *(const uint32_t*)&sBl[n0 + 8];
                mma_bf16(acc[0][nt], ah[0], bh);
                mma_bf16(acc[1][nt], ah[1], bh);
                mma_bf16(acc[0][nt], ah[0], bl);
                mma_bf16(acc[1][nt], ah[1], bl);
                mma_bf16(acc[0][nt], al[0], bh);
                mma_bf16(acc[1][nt], al[1], bh);
            }
        }
        __syncthreads();
    }

    /* epilogue */
#pragma unroll
    for (int mt = 0; mt < 2; mt++) {
        int r0 = bm + wm*32 + mt*16 + g;
#pragma unroll
        for (int nt = 0; nt < 8; nt++) {
            int c0 = bn + wn*64 + nt*8 + tg*2;
            if (r0 < M)
                *(float2*)(C + (long)r0*ldc + c0) =
                    make_float2(acc[mt][nt][0], acc[mt][nt][1]);
            if (r0 + 8 < M)
                *(float2*)(C + (long)(r0+8)*ldc + c0) =
                    make_float2(acc[mt][nt][2], acc[mt][nt][3]);
        }
    }
}

/* ------------------------- GAT: es/ed dots on raw x (warp/row) ---------------- */
__global__ __launch_bounds__(256) void k_esed(int L) {
    int w = blockIdx.x*8 + (threadIdx.x >> 5);
    if (w >= NB) return;
    int lane = threadIdx.x & 31;
    float4 x4 = *(const float4*)(g_seq + (long)w*384 + L*128 + lane*4);
    const float* base = g_wsd + L*512;
    float4 ws0 = *(const float4*)(base       + lane*4);
    float4 ws1 = *(const float4*)(base + 128 + lane*4);
    float4 wd0 = *(const float4*)(base + 256 + lane*4);
    float4 wd1 = *(const float4*)(base + 384 + lane*4);
    float v0 = wrsum(dot4(x4, ws0));
    float v1 = wrsum(dot4(x4, wd0));
    float v2 = wrsum(dot4(x4, ws1));
    float v3 = wrsum(dot4(x4, wd1));
    if (lane == 0) { g_es0[w] = v0; g_ed0[w] = v1; g_es1[w] = v2; g_ed1[w] = v3; }
}

/* ------------------------- GAT: softmax-mix in x-space (warp/row) -------------
   0.5 head-mean folded into the softmax normalizers. ---------------------------*/
__global__ __launch_bounds__(256) void k_gat_mix(int L) {
    int w = blockIdx.x*8 + (threadIdx.x >> 5);
    if (w >= NB) return;
    int lane = threadIdx.x & 31;
    int b = w / NN;
    int deg = g_adj_deg[w];
    const int* cols = g_adj_cols + (long)w * MAXDEG;
    int creg[4]; float e0r[4], e1r[4];
    float es0 = g_es0[w], es1 = g_es1[w];
    float m0 = -1e30f, m1 = -1e30f;
#pragma unroll
    for (int i = 0; i < 4; i++) {
        int j = i*32 + lane;
        creg[i] = 0; e0r[i] = -1e30f; e1r[i] = -1e30f;
        if (j < deg) {
            int c = cols[j]; creg[i] = c;
            float t0 = es0 + g_ed0[b*NN + c]; e0r[i] = (t0 > 0.f) ? t0 : 0.2f*t0;
            float t1 = es1 + g_ed1[b*NN + c]; e1r[i] = (t1 > 0.f) ? t1 : 0.2f*t1;
            m0 = fmaxf(m0, e0r[i]); m1 = fmaxf(m1, e1r[i]);
        }
    }
    m0 = wrmax(m0); m1 = wrmax(m1);
    float s0 = 0.f, s1 = 0.f;
    float p0r[4], p1r[4];
#pragma unroll
    for (int i = 0; i < 4; i++) {
        int j = i*32 + lane;
        p0r[i] = (j < deg) ? expf(e0r[i] - m0) : 0.f;
        p1r[i] = (j < deg) ? expf(e1r[i] - m1) : 0.f;
        s0 += p0r[i]; s1 += p1r[i];
    }
    s0 = wrsum(s0); s1 = wrsum(s1);
    float inv0 = 0.5f / s0, inv1 = 0.5f / s1;   /* fold head-mean */
    float4 a0 = make_float4(0.f, 0.f, 0.f, 0.f);
    float4 a1 = make_float4(0.f, 0.f, 0.f, 0.f);
    for (int i = 0; i < 4 && i*32 < deg; i++) {
        for (int l = 0; l < 32; l++) {
            int j = i*32 + l;
            if (j >= deg) break;                    /* uniform across warp */
            int   c  = __shfl_sync(0xffffffffu, creg[i], l);
            float w0 = __shfl_sync(0xffffffffu, p0r[i], l) * inv0;
            float w1 = __shfl_sync(0xffffffffu, p1r[i], l) * inv1;
            float4 x4 = *(const float4*)(g_seq + (long)(b*NN + c)*384 + L*128 + lane*4);
            a0.x += w0*x4.x; a0.y += w0*x4.y; a0.z += w0*x4.z; a0.w += w0*x4.w;
            a1.x += w1*x4.x; a1.y += w1*x4.y; a1.z += w1*x4.z; a1.w += w1*x4.w;
        }
    }
    *(float4*)(g_mix + (long)w*256       + lane*4) = a0;
    *(float4*)(g_mix + (long)w*256 + 128 + lane*4) = a1;
}

/* ------------------------- GAT: elu + normalize -> seq slot ------------------- */
__global__ __launch_bounds__(256) void k_gat_post(int lslot) {
    int w = blockIdx.x*8 + (threadIdx.x >> 5);
    if (w >= NB) return;
    int lane = threadIdx.x & 31;
    float4 mv = *(const float4*)(g_mv + (long)w*DD + lane*4);
    float4 ev;
    ev.x = (mv.x > 0.f) ? mv.x : expm1f(mv.x);
    ev.y = (mv.y > 0.f) ? mv.y : expm1f(mv.y);
    ev.z = (mv.z > 0.f) ? mv.z : expm1f(mv.z);
    ev.w = (mv.w > 0.f) ? mv.w : expm1f(mv.w);
    float ss = wrsum(dot4(ev, ev));
    float nrm = 1.f / fmaxf(sqrtf(ss), 1e-12f);
    *(float4*)(g_seq + ((long)w*3 + lslot)*DD + lane*4) =
        make_float4(ev.x*nrm, ev.y*nrm, ev.z*nrm, ev.w*nrm);
}

/* ------------------------- MHA: scores via y.x, mix x (warp/node) ------------- */
__global__ __launch_bounds__(256) void k_mha() {
    int w = blockIdx.x*8 + (threadIdx.x >> 5);
    if (w >= NB) return;
    int lane = threadIdx.x & 31;
    float4 x4[3], y4[3][2];
#pragma unroll
    for (int l = 0; l < 3; l++) {
        x4[l] = *(const float4*)(g_seq + (long)w*384 + l*128 + lane*4);
#pragma unroll
        for (int h = 0; h < 2; h++)
            y4[l][h] = *(const float4*)(g_y2 + (long)w*768 + l*256 + h*128 + lane*4);
    }
    float sc[2][3][3];
#pragma unroll
    for (int h = 0; h < 2; h++)
#pragma unroll
        for (int l = 0; l < 3; l++)
#pragma unroll
            for (int m = 0; m < 3; m++)
                sc[h][l][m] = wrsum(dot4(y4[l][h], x4[m])) * 0.08838834764831845f;
#pragma unroll
    for (int h = 0; h < 2; h++)
#pragma unroll
        for (int l = 0; l < 3; l++) {
            float a0 = sc[h][l][0], a1 = sc[h][l][1], a2 = sc[h][l][2];
            float m = fmaxf(a0, fmaxf(a1, a2));
            float e0 = expf(a0 - m), e1 = expf(a1 - m), e2 = expf(a2 - m);
            float inv = 1.f / (e0 + e1 + e2);
            e0 *= inv; e1 *= inv; e2 *= inv;
            float4 z;
            z.x = e0*x4[0].x + e1*x4[1].x + e2*x4[2].x;
            z.y = e0*x4[0].y + e1*x4[1].y + e2*x4[2].y;
            z.z = e0*x4[0].z + e1*x4[1].z + e2*x4[2].z;
            z.w = e0*x4[0].w + e1*x4[1].w + e2*x4[2].w;
            *(float4*)(g_z + (long)w*768 + l*256 + h*128 + lane*4) = z;
        }
}

/* ------------------------- residual + LN + mean (warp/row) -------------------- */
__global__ __launch_bounds__(256) void k_ln(const float* __restrict__ g,
                                            const float* __restrict__ bb,
                                            float* __restrict__ out) {
    int w = blockIdx.x*8 + (threadIdx.x >> 5);
    if (w >= NB) return;
    int lane = threadIdx.x & 31;
    int b = w / NN, row = w - b*NN;
    float4 g4 = *(const float4*)(g + lane*4);
    float4 b4 = *(const float4*)(bb + lane*4);
    float4 acc = make_float4(0.f, 0.f, 0.f, 0.f);
#pragma unroll
    for (int l = 0; l < 3; l++) {
        float4 v0 = *(const float4*)(g_of + ((long)w*3 + l)*DD + lane*4);
        float4 v1 = *(const float4*)(g_seq + ((long)w*3 + l)*DD + lane*4);
        float4 v = make_float4(v0.x+v1.x, v0.y+v1.y, v0.z+v1.z, v0.w+v1.w);
        float s  = wrsum(v.x + v.y + v.z + v.w);
        float s2 = wrsum(dot4(v, v));
        float mu  = s * (1.f/128.f);
        float var = s2 * (1.f/128.f) - mu*mu;
        float is = rsqrtf(var + 1e-6f);
        acc.x += g4.x*(v.x - mu)*is + b4.x;
        acc.y += g4.y*(v.y - mu)*is + b4.y;
        acc.z += g4.z*(v.z - mu)*is + b4.z;
        acc.w += g4.w*(v.w - mu)*is + b4.w;
    }
    float4 r = make_float4(acc.x*(1.f/3.f), acc.y*(1.f/3.f),
                           acc.z*(1.f/3.f), acc.w*(1.f/3.f));
    *(float4*)(out + (long)b*NN*256 + (long)row*256 + lane*4) = r;
}

/* ------------------------- HGC pieces (warp/row) ------------------------------ */
__global__ __launch_bounds__(256) void k_u0(const float* __restrict__ e0,
                                            const float* __restrict__ e1) {
    int w = blockIdx.x*8 + (threadIdx.x >> 5);
    if (w >= NB) return;
    int lane = threadIdx.x & 31;
    int b = w / NN, row = w - b*NN;
    float4 x = *(const float4*)((b ? e1 : e0) + (long)row*DD + lane*4);
    float s = wrsum(dot4(x, x));
    float n0 = fmaxf(sqrtf(s), 1e-15f);
    float ne = tanhf(n0);
    float pe = (ne > MAXN_) ? MAXN_/ne : 1.f;
    float np = fmaxf(ne*pe, 1e-15f);
    float c  = atanhf(fminf(np, 1.f - 1e-7f)) / np * (ne / n0) * pe;
    *(float4*)(g_u + (long)w*DD + lane*4) =
        make_float4(c*x.x, c*x.y, c*x.z, c*x.w);
}

__global__ __launch_bounds__(256) void k_hgc_bias(const float* __restrict__ T,
                                                  const float* __restrict__ bvec,
                                                  float* __restrict__ Y) {
    int w = blockIdx.x*8 + (threadIdx.x >> 5);
    if (w >= NB) return;
    int lane = threadIdx.x & 31;
    float4 t4 = *(const float4*)(T + (long)w*DD + lane*4);
    float4 b4 = *(const float4*)(bvec + lane*4);
    float s0 = wrsum(dot4(t4, t4));
    float s1 = wrsum(dot4(b4, b4));
    float s2 = wrsum(dot4(t4, b4));
    float nt = fmaxf(sqrtf(s0), 1e-15f);
    float et = tanhf(nt);
    float pt = (et > MAXN_) ? MAXN_/et : 1.f;
    float cm = (et/nt) * pt;
    float x2 = (et*pt) * (et*pt);
    float nb = fmaxf(sqrtf(s1), 1e-15f);
    float eb = tanhf(nb);
    float pb = (eb > MAXN_) ? MAXN_/eb : 1.f;
    float cb = (eb/nb) * pb;
    float y2 = (eb*pb) * (eb*pb);
    float xy = cm * cb * s2;
    float den = fmaxf(1.f + 2.f*xy + x2*y2, 1e-15f);
    float fA = (1.f + 2.f*xy + y2) * cm / den;
    float fB = (1.f - x2) * cb / den;
    float4 r = make_float4(fA*t4.x + fB*b4.x, fA*t4.y + fB*b4.y,
                           fA*t4.z + fB*b4.z, fA*t4.w + fB*b4.w);
    float s3 = wrsum(dot4(r, r));
    float nr = fmaxf(sqrtf(s3), 1e-15f);
    float pr = (nr > MAXN_) ? MAXN_/nr : 1.f;
    float np = fmaxf(nr*pr, 1e-15f);
    float c2 = atanhf(fminf(np, 1.f - 1e-7f)) / np * pr;
    *(float4*)(Y + (long)w*DD + lane*4) =
        make_float4(c2*r.x, c2*r.y, c2*r.z, c2*r.w);
}

__global__ __launch_bounds__(256) void k_hgc_agg(const float* __restrict__ Y,
                                                 float* __restrict__ W) {
    int w = blockIdx.x*8 + (threadIdx.x >> 5);
    if (w >= NB) return;
    int lane = threadIdx.x & 31;
    int b = w / NN;
    const int* cols = g_adj_cols + (long)w * MAXDEG;
    int deg = g_adj_deg[w];
    float4 acc = make_float4(0.f, 0.f, 0.f, 0.f);
    for (int j = 0; j < deg; j++) {
        int c = __ldg(&cols[j]);
        float4 v = *(const float4*)(Y + (long)(b*NN + c)*DD + lane*4);
        acc.x += v.x; acc.y += v.y; acc.z += v.z; acc.w += v.w;
    }
    float inv = 1.f / (float)deg;
    float4 z = make_float4(acc.x*inv, acc.y*inv, acc.z*inv, acc.w*inv);
    float4 rz = make_float4(fmaxf(z.x, 0.f), fmaxf(z.y, 0.f),
                            fmaxf(z.z, 0.f), fmaxf(z.w, 0.f));
    float s0 = wrsum(dot4(z, z));
    float s1 = wrsum(dot4(rz, rz));
    float nz = fmaxf(sqrtf(s0), 1e-15f);
    float e1 = tanhf(nz);
    float p1 = (e1 > MAXN_) ? MAXN_/e1 : 1.f;
    float cH = (e1/nz) * p1;
    float nH = fmaxf(e1*p1, 1e-15f);
    float cT = atanhf(fminf(nH, 1.f - 1e-7f)) / nH * cH;
    float nt2 = fmaxf(cT * sqrtf(s1), 1e-15f);
    float e2 = tanhf(nt2);
    float p2 = (e2 > MAXN_) ? MAXN_/e2 : 1.f;
    float hcoef = (e2/nt2) * p2 * cT;
    float nH2 = fmaxf(e2*p2, 1e-15f);
    float c2 = atanhf(fminf(nH2, 1.f - 1e-7f)) / nH2;
    float cc = c2 * hcoef;
    *(float4*)(W + (long)w*DD + lane*4) =
        make_float4(cc*rz.x, cc*rz.y, cc*rz.z, cc*rz.w);
}

__global__ __launch_bounds__(256) void k_hs(const float* __restrict__ e0,
                                            const float* __restrict__ e1,
                                            float* __restrict__ out) {
    int w = blockIdx.x*8 + (threadIdx.x >> 5);
    if (w >= NB) return;
    int lane = threadIdx.x & 31;
    int b = w / NN, row = w - b*NN;
    float4 e = *(const float4*)((b ? e1 : e0) + (long)row*DD + lane*4);
    float4 v = *(const float4*)(g_w2 + (long)w*DD + lane*4);
    *(float4*)(out + (long)(2+b)*NN*256 + (long)row*256 + lane*4) =
        make_float4(e.x+v.x, e.y+v.y, e.z+v.z, e.w+v.w);
}

/* ------------------------- host driver ----------------------------------------- */
extern "C" void kernel_launch(void* const* d_in, const int* in_sizes, int n_in,
                              void* d_out, int out_size) {
    const float* ent_sr    = (const float*)d_in[0];
    const float* ent_tg    = (const float*)d_in[1];
    const float* rel_sr    = (const float*)d_in[2];
    const float* rel_tg    = (const float*)d_in[3];
    const float* adj_sr    = (const float*)d_in[4];
    const float* adj_tg    = (const float*)d_in[5];
    const float* rel_adj_sr= (const float*)d_in[6];
    const float* rel_adj_tg= (const float*)d_in[7];
    const float* gat_W     = (const float*)d_in[8];
    const float* gat_a_src = (const float*)d_in[9];
    const float* gat_a_dst = (const float*)d_in[10];
    const float* Wq        = (const float*)d_in[11];
    const float* Wk        = (const float*)d_in[12];
    const float* Wv        = (const float*)d_in[13];
    const float* Wfc       = (const float*)d_in[14];
    const float* ln_g      = (const float*)d_in[15];
    const float* ln_b      = (const float*)d_in[16];
    const float* hgc_W     = (const float*)d_in[17];
    const float* hgc_b     = (const float*)d_in[18];
    float* out = (float*)d_out;

    float *seq, *mix, *mv, *y2, *z, *of, *u, *t, *y, *w, *w2, *Gt, *Pt, *Wgt;
    cudaGetSymbolAddress((void**)&seq, g_seq);
    cudaGetSymbolAddress((void**)&mix, g_mix);
    cudaGetSymbolAddress((void**)&mv,  g_mv);
    cudaGetSymbolAddress((void**)&y2,  g_y2);
    cudaGetSymbolAddress((void**)&z,   g_z);
    cudaGetSymbolAddress((void**)&of,  g_of);
    cudaGetSymbolAddress((void**)&u,   g_u);
    cudaGetSymbolAddress((void**)&t,   g_t);
    cudaGetSymbolAddress((void**)&y,   g_y);
    cudaGetSymbolAddress((void**)&w,   g_w);
    cudaGetSymbolAddress((void**)&w2,  g_w2);
    cudaGetSymbolAddress((void**)&Gt,  g_Gt);
    cudaGetSymbolAddress((void**)&Pt,  g_Pt);
    cudaGetSymbolAddress((void**)&Wgt, g_Wgt);

    dim3 gGAT(1, 94);      /* [12000,256]@Wgt^T -> N=128 */
    dim3 gY  (2, 282);     /* [36000,128]@Gt^T  -> N=256 */
    dim3 gOF (1, 282);     /* [36000,256]@Pt^T  -> N=128 */
    dim3 gHGC(1, 94);

    /* sparsify + precompute */
    k_build_adj<<<dim3(NN, 2), 256>>>(adj_sr, adj_tg);
    k_build_rel<<<dim3(NN, 2), 256>>>(rel_adj_sr, rel_adj_tg);
    k_relagg<<<NWB, 256>>>(rel_sr, rel_tg, out);
    k_seq0<<<NWB, 256>>>(ent_sr, ent_tg);
    k_precomp_Gt<<<256, 128>>>(Wq, Wk);
    k_precomp_Pt<<<256, 128>>>(Wv, Wfc);
    k_precomp_gat<<<8, 128>>>(gat_W, gat_a_src, gat_a_dst);
    k_precomp_Wgt<<<256, 256>>>(gat_W);

    /* GAT x2: attention on raw x, mix in x-space, HMMA GEMM, post */
    for (int L = 0; L < 2; L++) {
        k_esed<<<NWB, 256>>>(L);
        k_gat_mix<<<NWB, 256>>>(L);
        k_hmma<<<gGAT, 256>>>(mix, 256, Wgt + (long)L*128*256, 256,
                              mv, 128, 12000, 256);
        k_gat_post<<<NWB, 256>>>(L + 1);
    }

    /* MHA: y = x@G (via Gt), per-node attention+mix, of = z@P (via Pt) */
    k_hmma<<<gY, 256>>>(seq, 128, Gt, 128, y2, 256, 36000, 128);
    k_mha<<<NWB, 256>>>();
    k_hmma<<<gOF, 256>>>(z, 256, Pt, 256, of, 128, 36000, 256);
    k_ln<<<NWB, 256>>>(ln_g, ln_b, out);

    /* HGC encoder (hgc_W rows are already [n][k] for A@W^T) */
    k_u0<<<NWB, 256>>>(ent_sr, ent_tg);
    k_hmma<<<gHGC, 256>>>(u, 128, hgc_W, 128, t, 128, 12000, 128);
    k_hgc_bias<<<NWB, 256>>>(t, hgc_b, y);
    k_hgc_agg<<<NWB, 256>>>(y, w);
    k_hmma<<<gHGC, 256>>>(w, 128, hgc_W + DD*DD, 128, t, 128, 12000, 128);
    k_hgc_bias<<<NWB, 256>>>(t, hgc_b + DD, y);
    k_hgc_agg<<<NWB, 256>>>(y, w2);
    k_hs<<<NWB, 256>>>(ent_sr, ent_tg, out);
}